// round 1
// baseline (speedup 1.0000x reference)
#include <cuda_runtime.h>
#include <math.h>

#define CHI 64
#define CHO 64
#define B_  4
#define H_  128
#define W_  256
#define HW  (H_*W_)

// scratch for offset/mask conv output: [B, 27, H, W]
__device__ float g_om[(size_t)B_ * 27 * H_ * W_];

// ---------------------------------------------------------------------------
// Kernel 1: offset/mask conv (3x3, 64 -> 27 channels, pad 1)
// block = one output row (256 threads), thread = one pixel, 27(+1 pad) accs.
// ---------------------------------------------------------------------------
__global__ __launch_bounds__(256) void offset_conv_kernel(
    const float* __restrict__ x,
    const float* __restrict__ w_off,
    const float* __restrict__ b_off)
{
    extern __shared__ float sw[];   // [9][64][28], oc-padded to 28 for float4
    const int tid = threadIdx.x;

    // transpose-load weights: w_off[(oc*64+ci)*9+k] -> sw[(k*64+ci)*28+oc]
    for (int i = tid; i < 27 * 64 * 9; i += 256) {
        int oc  = i / 576;
        int rem = i - oc * 576;
        int ci  = rem / 9;
        int k   = rem - ci * 9;
        sw[(k * 64 + ci) * 28 + oc] = w_off[i];
    }
    for (int i = tid; i < 9 * 64; i += 256) sw[i * 28 + 27] = 0.0f;
    __syncthreads();

    const int h  = blockIdx.x;
    const int b  = blockIdx.y;
    const int wo = tid;

    float acc[28];
    #pragma unroll
    for (int oc = 0; oc < 27; oc++) acc[oc] = __ldg(b_off + oc);
    acc[27] = 0.0f;

    const float* xb = x + (size_t)b * CHI * HW;

    #pragma unroll
    for (int ky = 0; ky < 3; ky++) {
        const int y = h - 1 + ky;
        if (y < 0 || y >= H_) continue;
        #pragma unroll
        for (int kx = 0; kx < 3; kx++) {
            const int xx = wo - 1 + kx;
            if (xx < 0 || xx >= W_) continue;
            const int k = ky * 3 + kx;
            const float* xp = xb + y * W_ + xx;
            #pragma unroll 4
            for (int ci = 0; ci < 64; ci++) {
                const float v = __ldg(xp + ci * HW);
                const float4* w4 = (const float4*)(sw + (k * 64 + ci) * 28);
                #pragma unroll
                for (int t = 0; t < 7; t++) {
                    float4 w = w4[t];
                    acc[4*t+0] += v * w.x;
                    acc[4*t+1] += v * w.y;
                    acc[4*t+2] += v * w.z;
                    acc[4*t+3] += v * w.w;
                }
            }
        }
    }

    float* omp = g_om + ((size_t)b * 27 * H_ + h) * W_ + wo;
    #pragma unroll
    for (int oc = 0; oc < 27; oc++) omp[(size_t)oc * HW] = acc[oc];
}

// ---------------------------------------------------------------------------
// Kernel 2: deformable conv main contraction.
// block = 128 pixels (half row), thread = one pixel, 64 output-channel accs.
// Main weight staged in smem as [k][ci][co] (147456 B), float4 broadcast reads.
// ---------------------------------------------------------------------------
__global__ __launch_bounds__(128, 1) void dcn_main_kernel(
    const float* __restrict__ x,
    const float* __restrict__ weight,
    const float* __restrict__ bias,
    float* __restrict__ out)
{
    extern __shared__ float sw[];   // [9][64][64]
    __shared__ float sbias[64];
    const int tid = threadIdx.x;

    // transpose-load: weight[(co*64+ci)*9+k] -> sw[(k*64+ci)*64+co]
    for (int i = tid; i < CHO * CHI * 9; i += 128) {
        int co  = i / 576;
        int rem = i - co * 576;
        int ci  = rem / 9;
        int k   = rem - ci * 9;
        sw[(k * 64 + ci) * 64 + co] = weight[i];
    }
    if (tid < 64) sbias[tid] = bias[tid];
    __syncthreads();

    const int half = blockIdx.x;
    const int h    = blockIdx.y;
    const int b    = blockIdx.z;
    const int wo   = half * 128 + tid;

    const float* omp = g_om + ((size_t)b * 27 * H_ + h) * W_ + wo;
    const float* xb  = x + (size_t)b * CHI * HW;

    float acc[64];
    #pragma unroll
    for (int co = 0; co < 64; co++) acc[co] = sbias[co];

    #pragma unroll 1
    for (int k = 0; k < 9; k++) {
        // per-tap sampling params
        const float oy = omp[(size_t)(2 * k)     * HW];
        const float ox = omp[(size_t)(2 * k + 1) * HW];
        const float mz = omp[(size_t)(18 + k)    * HW];
        const float m  = 1.0f / (1.0f + expf(-mz));

        const float sy = (float)(h  - 1 + k / 3) + oy;
        const float sx = (float)(wo - 1 + k % 3) + ox;

        const float y0f = floorf(sy);
        const float x0f = floorf(sx);
        const float dy  = sy - y0f;
        const float dx  = sx - x0f;
        const int y0 = (int)y0f, x0 = (int)x0f;
        const int y1 = y0 + 1,  x1 = x0 + 1;

        const bool vy0 = (y0 >= 0) && (y0 < H_);
        const bool vy1 = (y1 >= 0) && (y1 < H_);
        const bool vx0 = (x0 >= 0) && (x0 < W_);
        const bool vx1 = (x1 >= 0) && (x1 < W_);

        float w00 = (1.0f - dy) * (1.0f - dx) * m;
        float w01 = (1.0f - dy) * dx * m;
        float w10 = dy * (1.0f - dx) * m;
        float w11 = dy * dx * m;
        if (!(vy0 && vx0)) w00 = 0.0f;
        if (!(vy0 && vx1)) w01 = 0.0f;
        if (!(vy1 && vx0)) w10 = 0.0f;
        if (!(vy1 && vx1)) w11 = 0.0f;

        const int cy0 = min(max(y0, 0), H_ - 1);
        const int cy1 = min(max(y1, 0), H_ - 1);
        const int cx0 = min(max(x0, 0), W_ - 1);
        const int cx1 = min(max(x1, 0), W_ - 1);

        const int i00 = cy0 * W_ + cx0;
        const int i01 = cy0 * W_ + cx1;
        const int i10 = cy1 * W_ + cx0;
        const int i11 = cy1 * W_ + cx1;

        const float4* swk = (const float4*)(sw + (size_t)k * 64 * 64);

        #pragma unroll 8
        for (int ci = 0; ci < 64; ci++) {
            const float* xc = xb + ci * HW;
            const float v = w00 * __ldg(xc + i00)
                          + w01 * __ldg(xc + i01)
                          + w10 * __ldg(xc + i10)
                          + w11 * __ldg(xc + i11);
            const float4* w4 = swk + ci * 16;
            #pragma unroll
            for (int t = 0; t < 16; t++) {
                float4 w = w4[t];
                acc[4*t+0] += v * w.x;
                acc[4*t+1] += v * w.y;
                acc[4*t+2] += v * w.z;
                acc[4*t+3] += v * w.w;
            }
        }
    }

    float* op = out + ((size_t)b * CHO * H_ + h) * W_ + wo;
    #pragma unroll
    for (int co = 0; co < 64; co++) op[(size_t)co * HW] = acc[co];
}

// ---------------------------------------------------------------------------
extern "C" void kernel_launch(void* const* d_in, const int* in_sizes, int n_in,
                              void* d_out, int out_size)
{
    const float* x      = (const float*)d_in[0];
    const float* w_off  = (const float*)d_in[1];
    const float* b_off  = (const float*)d_in[2];
    const float* weight = (const float*)d_in[3];
    const float* bias   = (const float*)d_in[4];
    float* out = (float*)d_out;

    cudaFuncSetAttribute(offset_conv_kernel,
                         cudaFuncAttributeMaxDynamicSharedMemorySize,
                         9 * 64 * 28 * (int)sizeof(float));
    cudaFuncSetAttribute(dcn_main_kernel,
                         cudaFuncAttributeMaxDynamicSharedMemorySize,
                         9 * 64 * 64 * (int)sizeof(float));

    offset_conv_kernel<<<dim3(H_, B_), 256, 9 * 64 * 28 * sizeof(float)>>>(
        x, w_off, b_off);
    dcn_main_kernel<<<dim3(2, H_, B_), 128, 9 * 64 * 64 * sizeof(float)>>>(
        x, weight, bias, out);
}

// round 3
// speedup vs baseline: 1.5283x; 1.5283x over previous
#include <cuda_runtime.h>
#include <math.h>

#define CHI 64
#define CHO 64
#define B_  4
#define H_  128
#define W_  256
#define HW  (H_*W_)
#define KC  16
#define VS  132   // padded v_s row stride (floats)

// scratch: offset/mask conv output [B, 27, H, W]
__device__ float g_om[(size_t)B_ * 27 * H_ * W_];
// scratch: transposed main weight [k][ci][co]
__device__ float g_wT[9 * CHI * CHO];

// ---------------------------------------------------------------------------
// tiny kernel: transpose weight[co][ci][k] -> g_wT[k][ci][co]
// ---------------------------------------------------------------------------
__global__ void transpose_w_kernel(const float* __restrict__ weight)
{
    int i = blockIdx.x * 256 + threadIdx.x;
    if (i < CHO * CHI * 9) {
        int co  = i / 576;
        int rem = i - co * 576;
        int ci  = rem / 9;
        int k   = rem - ci * 9;
        g_wT[(k * CHI + ci) * CHO + co] = weight[i];
    }
}

// ---------------------------------------------------------------------------
// Kernel 1: offset/mask conv (3x3, 64 -> 27 channels, pad 1)
// ---------------------------------------------------------------------------
__global__ __launch_bounds__(256) void offset_conv_kernel(
    const float* __restrict__ x,
    const float* __restrict__ w_off,
    const float* __restrict__ b_off)
{
    extern __shared__ float sw[];   // [9][64][28]
    const int tid = threadIdx.x;

    for (int i = tid; i < 27 * 64 * 9; i += 256) {
        int oc  = i / 576;
        int rem = i - oc * 576;
        int ci  = rem / 9;
        int k   = rem - ci * 9;
        sw[(k * 64 + ci) * 28 + oc] = w_off[i];
    }
    for (int i = tid; i < 9 * 64; i += 256) sw[i * 28 + 27] = 0.0f;
    __syncthreads();

    const int h  = blockIdx.x;
    const int b  = blockIdx.y;
    const int wo = tid;

    float acc[28];
    #pragma unroll
    for (int oc = 0; oc < 27; oc++) acc[oc] = __ldg(b_off + oc);
    acc[27] = 0.0f;

    const float* xb = x + (size_t)b * CHI * HW;

    #pragma unroll
    for (int ky = 0; ky < 3; ky++) {
        const int y = h - 1 + ky;
        if (y < 0 || y >= H_) continue;
        #pragma unroll
        for (int kx = 0; kx < 3; kx++) {
            const int xx = wo - 1 + kx;
            if (xx < 0 || xx >= W_) continue;
            const int k = ky * 3 + kx;
            const float* xp = xb + y * W_ + xx;
            #pragma unroll 4
            for (int ci = 0; ci < 64; ci++) {
                const float v = __ldg(xp + ci * HW);
                const float4* w4 = (const float4*)(sw + (k * 64 + ci) * 28);
                #pragma unroll
                for (int t = 0; t < 7; t++) {
                    float4 w = w4[t];
                    acc[4*t+0] += v * w.x;
                    acc[4*t+1] += v * w.y;
                    acc[4*t+2] += v * w.z;
                    acc[4*t+3] += v * w.w;
                }
            }
        }
    }

    float* omp = g_om + ((size_t)b * 27 * H_ + h) * W_ + wo;
    #pragma unroll
    for (int oc = 0; oc < 27; oc++) omp[(size_t)oc * HW] = acc[oc];
}

// ---------------------------------------------------------------------------
// Kernel 2: deformable conv as a staged register-tiled GEMM.
// Block = 128 threads = tile [64 co x 128 pix]; thread tile 8co x 8pix.
// Per (k, 16-ci chunk): gather+bilinear 16x128 v into smem, 16x64 weight
// slice into smem, then GEMM. Double-buffered, one sync per chunk.
// ---------------------------------------------------------------------------
__global__ __launch_bounds__(128, 3) void dcn_main_kernel(
    const float* __restrict__ x,
    const float* __restrict__ bias,
    float* __restrict__ out)
{
    __shared__ float v_s[2][KC][VS];
    __shared__ float w_s[2][KC][64];

    const int tid  = threadIdx.x;
    const int half = blockIdx.x;
    const int h    = blockIdx.y;
    const int b    = blockIdx.z;
    const int wo   = half * 128 + tid;     // this thread's pixel (sampling role)

    const int cg = tid & 7;                // co group (8 groups of 8)
    const int pg = tid >> 3;               // pix group (16 groups of 8)

    const float* omp = g_om + ((size_t)b * 27 * H_ + h) * W_ + wo;
    const float* xb  = x + (size_t)b * CHI * HW;

    float acc[8][8];
    #pragma unroll
    for (int c = 0; c < 8; c++) {
        const float bv = __ldg(bias + cg * 8 + c);
        #pragma unroll
        for (int p = 0; p < 8; p++) acc[c][p] = bv;
    }

    int buf = 0;
    #pragma unroll 1
    for (int k = 0; k < 9; k++) {
        // ---- sampling params for this thread's pixel ----
        const float oy = omp[(size_t)(2 * k)     * HW];
        const float ox = omp[(size_t)(2 * k + 1) * HW];
        const float mz = omp[(size_t)(18 + k)    * HW];
        const float m  = 1.0f / (1.0f + expf(-mz));

        const float sy = (float)(h  - 1 + k / 3) + oy;
        const float sx = (float)(wo - 1 + k % 3) + ox;

        const float y0f = floorf(sy);
        const float x0f = floorf(sx);
        const float dy  = sy - y0f;
        const float dx  = sx - x0f;
        const int y0 = (int)y0f, x0 = (int)x0f;
        const int y1 = y0 + 1,  x1 = x0 + 1;

        const bool vy0 = (y0 >= 0) && (y0 < H_);
        const bool vy1 = (y1 >= 0) && (y1 < H_);
        const bool vx0 = (x0 >= 0) && (x0 < W_);
        const bool vx1 = (x1 >= 0) && (x1 < W_);

        float w00 = (1.0f - dy) * (1.0f - dx) * m;
        float w01 = (1.0f - dy) * dx * m;
        float w10 = dy * (1.0f - dx) * m;
        float w11 = dy * dx * m;
        if (!(vy0 && vx0)) w00 = 0.0f;
        if (!(vy0 && vx1)) w01 = 0.0f;
        if (!(vy1 && vx0)) w10 = 0.0f;
        if (!(vy1 && vx1)) w11 = 0.0f;

        const int cy0 = min(max(y0, 0), H_ - 1);
        const int cy1 = min(max(y1, 0), H_ - 1);
        const int cx0 = min(max(x0, 0), W_ - 1);
        const int cx1 = min(max(x1, 0), W_ - 1);

        const float* p00 = xb + cy0 * W_ + cx0;
        const float* p01 = xb + cy0 * W_ + cx1;
        const float* p10 = xb + cy1 * W_ + cx0;
        const float* p11 = xb + cy1 * W_ + cx1;

        #pragma unroll 1
        for (int cc = 0; cc < 4; cc++) {
            const int ci0 = cc * KC;

            // ---- load 16x64 weight slice, coalesced float4 ----
            const float4* wsrc = (const float4*)(g_wT + (k * CHI + ci0) * CHO);
            float4* wdst = (float4*)w_s[buf];
            wdst[tid]       = wsrc[tid];
            wdst[tid + 128] = wsrc[tid + 128];

            // ---- gather + bilinear: 16 ci for this thread's pixel ----
            const float* q00 = p00 + ci0 * HW;
            const float* q01 = p01 + ci0 * HW;
            const float* q10 = p10 + ci0 * HW;
            const float* q11 = p11 + ci0 * HW;
            #pragma unroll
            for (int r = 0; r < KC; r++) {
                const float v = w00 * __ldg(q00 + r * HW)
                              + w01 * __ldg(q01 + r * HW)
                              + w10 * __ldg(q10 + r * HW)
                              + w11 * __ldg(q11 + r * HW);
                v_s[buf][r][tid] = v;
            }

            __syncthreads();

            // ---- register-tiled GEMM: acc[8co][8pix] += w x v ----
            #pragma unroll 8
            for (int r = 0; r < KC; r++) {
                const float4 va = *(const float4*)&v_s[buf][r][pg * 8];
                const float4 vb = *(const float4*)&v_s[buf][r][pg * 8 + 4];
                const float4 wa = *(const float4*)&w_s[buf][r][cg * 8];
                const float4 wb = *(const float4*)&w_s[buf][r][cg * 8 + 4];
                const float vv[8] = {va.x, va.y, va.z, va.w, vb.x, vb.y, vb.z, vb.w};
                const float ww[8] = {wa.x, wa.y, wa.z, wa.w, wb.x, wb.y, wb.z, wb.w};
                #pragma unroll
                for (int c = 0; c < 8; c++)
                    #pragma unroll
                    for (int p = 0; p < 8; p++)
                        acc[c][p] += ww[c] * vv[p];
            }

            buf ^= 1;
        }
    }

    // ---- writeout: thread owns co cg*8..+7, pixels half*128 + pg*8..+7 ----
    #pragma unroll
    for (int c = 0; c < 8; c++) {
        float* op = out + ((size_t)(b * CHO + cg * 8 + c) * H_ + h) * W_
                  + half * 128 + pg * 8;
        *(float4*)op       = make_float4(acc[c][0], acc[c][1], acc[c][2], acc[c][3]);
        *((float4*)op + 1) = make_float4(acc[c][4], acc[c][5], acc[c][6], acc[c][7]);
    }
}

// ---------------------------------------------------------------------------
extern "C" void kernel_launch(void* const* d_in, const int* in_sizes, int n_in,
                              void* d_out, int out_size)
{
    const float* x      = (const float*)d_in[0];
    const float* w_off  = (const float*)d_in[1];
    const float* b_off  = (const float*)d_in[2];
    const float* weight = (const float*)d_in[3];
    const float* bias   = (const float*)d_in[4];
    float* out = (float*)d_out;

    cudaFuncSetAttribute(offset_conv_kernel,
                         cudaFuncAttributeMaxDynamicSharedMemorySize,
                         9 * 64 * 28 * (int)sizeof(float));

    transpose_w_kernel<<<(CHO * CHI * 9 + 255) / 256, 256>>>(weight);
    offset_conv_kernel<<<dim3(H_, B_), 256, 9 * 64 * 28 * sizeof(float)>>>(
        x, w_off, b_off);
    dcn_main_kernel<<<dim3(2, H_, B_), 128>>>(x, bias, out);
}

// round 5
// speedup vs baseline: 1.8640x; 1.2196x over previous
#include <cuda_runtime.h>
#include <math.h>
#include <stdint.h>

#define CHI 64
#define CHO 64
#define B_  4
#define H_  128
#define W_  256
#define HW  (H_*W_)

#define SAS 68          // smem row stride (floats) for A and B tiles
#define SM_A_FL 0       // A tile: 128 x 68 floats
#define SM_B_FL 8704    // B tile: 64 x 68 floats (A is 8704 floats)
#define SM_TOTAL ((8704 + 64*68) * 4)   // 52224 bytes

// scratch: offset/mask conv output [B, 27, H, W]
__device__ float g_om[(size_t)B_ * 27 * H_ * W_];
// scratch: main weight as [tap][co][ci]
__device__ float g_wT[9 * CHO * CHI];

// ---------------------------------------------------------------------------
__device__ __forceinline__ uint32_t f2tf32(float x) {
    uint32_t u; asm("cvt.rna.tf32.f32 %0, %1;" : "=r"(u) : "f"(x)); return u;
}
__device__ __forceinline__ void split_tf32(float v, uint32_t& hi, uint32_t& lo) {
    uint32_t h = f2tf32(v);
    float r = v - __uint_as_float(h);
    hi = h;
    lo = f2tf32(r);
}
__device__ __forceinline__ void mma8(float* d, const uint32_t* a,
                                     uint32_t b0, uint32_t b1) {
    asm volatile(
        "mma.sync.aligned.m16n8k8.row.col.f32.tf32.tf32.f32 "
        "{%0,%1,%2,%3}, {%4,%5,%6,%7}, {%8,%9}, {%0,%1,%2,%3};"
        : "+f"(d[0]), "+f"(d[1]), "+f"(d[2]), "+f"(d[3])
        : "r"(a[0]), "r"(a[1]), "r"(a[2]), "r"(a[3]), "r"(b0), "r"(b1));
}

// ---------------------------------------------------------------------------
// prep: weight[co][ci][k] -> g_wT[tap][co][ci]
// ---------------------------------------------------------------------------
__global__ void prep_weights_kernel(const float* __restrict__ w)
{
    int i = blockIdx.x * 256 + threadIdx.x;      // 9*64*64 = 36864
    if (i >= 9 * 64 * 64) return;
    int tap = i / 4096;
    int rem = i - tap * 4096;
    int co  = rem >> 6;
    int ci  = rem & 63;
    g_wT[tap * 4096 + co * 64 + ci] = w[(co * 64 + ci) * 9 + tap];
}

// ---------------------------------------------------------------------------
// Kernel 1: offset/mask conv (3x3, 64 -> 27 channels, pad 1)  [unchanged]
// ---------------------------------------------------------------------------
__global__ __launch_bounds__(256) void offset_conv_kernel(
    const float* __restrict__ x,
    const float* __restrict__ w_off,
    const float* __restrict__ b_off)
{
    extern __shared__ float sw[];   // [9][64][28]
    const int tid = threadIdx.x;

    for (int i = tid; i < 27 * 64 * 9; i += 256) {
        int oc  = i / 576;
        int rem = i - oc * 576;
        int ci  = rem / 9;
        int k   = rem - ci * 9;
        sw[(k * 64 + ci) * 28 + oc] = w_off[i];
    }
    for (int i = tid; i < 9 * 64; i += 256) sw[i * 28 + 27] = 0.0f;
    __syncthreads();

    const int h  = blockIdx.x;
    const int b  = blockIdx.y;
    const int wo = tid;

    float acc[28];
    #pragma unroll
    for (int oc = 0; oc < 27; oc++) acc[oc] = __ldg(b_off + oc);
    acc[27] = 0.0f;

    const float* xb = x + (size_t)b * CHI * HW;

    #pragma unroll
    for (int ky = 0; ky < 3; ky++) {
        const int y = h - 1 + ky;
        if (y < 0 || y >= H_) continue;
        #pragma unroll
        for (int kx = 0; kx < 3; kx++) {
            const int xx = wo - 1 + kx;
            if (xx < 0 || xx >= W_) continue;
            const int k = ky * 3 + kx;
            const float* xp = xb + y * W_ + xx;
            #pragma unroll 4
            for (int ci = 0; ci < 64; ci++) {
                const float v = __ldg(xp + ci * HW);
                const float4* w4 = (const float4*)(sw + (k * 64 + ci) * 28);
                #pragma unroll
                for (int t = 0; t < 7; t++) {
                    float4 w = w4[t];
                    acc[4*t+0] += v * w.x;
                    acc[4*t+1] += v * w.y;
                    acc[4*t+2] += v * w.z;
                    acc[4*t+3] += v * w.w;
                }
            }
        }
    }

    float* omp = g_om + ((size_t)b * 27 * H_ + h) * W_ + wo;
    #pragma unroll
    for (int oc = 0; oc < 27; oc++) omp[(size_t)oc * HW] = acc[oc];
}

// ---------------------------------------------------------------------------
// Kernel 2: deformable conv main GEMM on mma.sync tf32 (3-term split).
// Block = 128 threads = [128 pix (M)] x [64 co (N)], K = 576 over 9 taps.
// Warp w owns pixels w*32..w*32+31 (2 m-frags of 16) x all 8 n-frags.
// A[pix][ci] fp32 in smem stride 68 (frag LDS conflict-free: bank=(4g+t)).
// ---------------------------------------------------------------------------
__global__ __launch_bounds__(128, 3) void dcn_main_kernel(
    const float* __restrict__ x,
    const float* __restrict__ bias,
    float* __restrict__ out)
{
    extern __shared__ float smf[];
    float* As = smf + SM_A_FL;
    float* Bs = smf + SM_B_FL;

    const int tid  = threadIdx.x;
    const int wid  = tid >> 5;
    const int lid  = tid & 31;
    const int g    = lid >> 2;     // mma groupID
    const int t    = lid & 3;      // mma thread-in-group
    const int hblk = blockIdx.x;
    const int h    = blockIdx.y;
    const int b    = blockIdx.z;
    const int wo   = hblk * 128 + tid;   // this thread's pixel (gather role)

    const float* omp = g_om + ((size_t)b * 27 * H_ + h) * W_ + wo;
    const float* xb  = x + (size_t)b * CHI * HW;

    float acc[2][8][4];
    #pragma unroll
    for (int m = 0; m < 2; m++)
        #pragma unroll
        for (int n = 0; n < 8; n++)
            #pragma unroll
            for (int e = 0; e < 4; e++) acc[m][n][e] = 0.0f;

    #pragma unroll 1
    for (int tap = 0; tap < 9; tap++) {
        if (tap) __syncthreads();

        // ---- copy B tile [64co][64ci] -> smem stride 68 ----
        {
            const float4* bsrc = (const float4*)(g_wT + tap * 4096);
            #pragma unroll
            for (int j = 0; j < 8; j++) {
                const int lin = tid + j * 128;       // float4 index, 1024 total
                const float4 val = bsrc[lin];
                const int co = lin >> 4;
                const int c4 = lin & 15;
                *(float4*)(Bs + co * SAS + c4 * 4) = val;
            }
        }

        // ---- sampling params for this thread's pixel ----
        const float oy = omp[(size_t)(2 * tap)     * HW];
        const float ox = omp[(size_t)(2 * tap + 1) * HW];
        const float mz = omp[(size_t)(18 + tap)    * HW];
        const float m  = 1.0f / (1.0f + expf(-mz));

        const float sy = (float)(h  - 1 + tap / 3) + oy;
        const float sx = (float)(wo - 1 + tap % 3) + ox;

        const float y0f = floorf(sy);
        const float x0f = floorf(sx);
        const float dy  = sy - y0f;
        const float dx  = sx - x0f;
        const int y0 = (int)y0f, x0 = (int)x0f;
        const int y1 = y0 + 1,  x1 = x0 + 1;

        const bool vy0 = (y0 >= 0) && (y0 < H_);
        const bool vy1 = (y1 >= 0) && (y1 < H_);
        const bool vx0 = (x0 >= 0) && (x0 < W_);
        const bool vx1 = (x1 >= 0) && (x1 < W_);

        float w00 = (1.0f - dy) * (1.0f - dx) * m;
        float w01 = (1.0f - dy) * dx * m;
        float w10 = dy * (1.0f - dx) * m;
        float w11 = dy * dx * m;
        if (!(vy0 && vx0)) w00 = 0.0f;
        if (!(vy0 && vx1)) w01 = 0.0f;
        if (!(vy1 && vx0)) w10 = 0.0f;
        if (!(vy1 && vx1)) w11 = 0.0f;

        const int cy0 = min(max(y0, 0), H_ - 1);
        const int cy1 = min(max(y1, 0), H_ - 1);
        const int cx0 = min(max(x0, 0), W_ - 1);
        const int cx1 = min(max(x1, 0), W_ - 1);

        const float* p00 = xb + cy0 * W_ + cx0;
        const float* p01 = xb + cy0 * W_ + cx1;
        const float* p10 = xb + cy1 * W_ + cx0;
        const float* p11 = xb + cy1 * W_ + cx1;

        // ---- gather + bilinear: 64 ci for this pixel -> A[tid][ci] ----
        #pragma unroll
        for (int j = 0; j < 16; j++) {
            float4 v4;
            #pragma unroll
            for (int e = 0; e < 4; e++) {
                const int ci = j * 4 + e;
                ((float*)&v4)[e] = w00 * __ldg(p00 + ci * HW)
                                 + w01 * __ldg(p01 + ci * HW)
                                 + w10 * __ldg(p10 + ci * HW)
                                 + w11 * __ldg(p11 + ci * HW);
            }
            *(float4*)(As + tid * SAS + j * 4) = v4;
        }

        __syncthreads();

        // ---- warp-level tf32 MMA: 8 k-steps x 8 n-frags x (2m x 3 terms) ----
        #pragma unroll 1
        for (int kk = 0; kk < 8; kk++) {
            const int col = kk * 8 + t;
            uint32_t ah[2][4], al[2][4];
            #pragma unroll
            for (int mi = 0; mi < 2; mi++) {
                const float* ab = As + (wid * 32 + mi * 16 + g) * SAS + col;
                split_tf32(ab[0],           ah[mi][0], al[mi][0]);
                split_tf32(ab[8 * SAS],     ah[mi][1], al[mi][1]);
                split_tf32(ab[4],           ah[mi][2], al[mi][2]);
                split_tf32(ab[8 * SAS + 4], ah[mi][3], al[mi][3]);
            }
            #pragma unroll
            for (int n = 0; n < 8; n++) {
                const float* bb = Bs + (n * 8 + g) * SAS + col;
                uint32_t bh0, bl0, bh1, bl1;
                split_tf32(bb[0], bh0, bl0);
                split_tf32(bb[4], bh1, bl1);
                mma8(acc[0][n], ah[0], bh0, bh1);
                mma8(acc[1][n], ah[1], bh0, bh1);
                mma8(acc[0][n], al[0], bh0, bh1);
                mma8(acc[1][n], al[1], bh0, bh1);
                mma8(acc[0][n], ah[0], bl0, bl1);
                mma8(acc[1][n], ah[1], bl0, bl1);
            }
        }
    }

    // ---- epilogue: stage D through this warp's own A rows (8704 B) ----
    float* ds = As + wid * 2176;           // [64 co][34] per warp
    #pragma unroll
    for (int mi = 0; mi < 2; mi++) {
        #pragma unroll
        for (int n = 0; n < 8; n++) {
            const int co = n * 8 + 2 * t;
            const int p  = mi * 16 + g;
            ds[co * 34 + p]           = acc[mi][n][0];
            ds[(co + 1) * 34 + p]     = acc[mi][n][1];
            ds[co * 34 + p + 8]       = acc[mi][n][2];
            ds[(co + 1) * 34 + p + 8] = acc[mi][n][3];
        }
    }
    __syncwarp();

    const int pixbase = hblk * 128 + wid * 32;
    #pragma unroll 8
    for (int co = 0; co < 64; co++) {
        out[((size_t)(b * CHO + co) * H_ + h) * W_ + pixbase + lid] =
            ds[co * 34 + lid] + __ldg(bias + co);
    }
}

// ---------------------------------------------------------------------------
extern "C" void kernel_launch(void* const* d_in, const int* in_sizes, int n_in,
                              void* d_out, int out_size)
{
    const float* x      = (const float*)d_in[0];
    const float* w_off  = (const float*)d_in[1];
    const float* b_off  = (const float*)d_in[2];
    const float* weight = (const float*)d_in[3];
    const float* bias   = (const float*)d_in[4];
    float* out = (float*)d_out;

    cudaFuncSetAttribute(offset_conv_kernel,
                         cudaFuncAttributeMaxDynamicSharedMemorySize,
                         9 * 64 * 28 * (int)sizeof(float));
    cudaFuncSetAttribute(dcn_main_kernel,
                         cudaFuncAttributeMaxDynamicSharedMemorySize, SM_TOTAL);

    prep_weights_kernel<<<(9 * 64 * 64 + 255) / 256, 256>>>(weight);
    offset_conv_kernel<<<dim3(H_, B_), 256, 9 * 64 * 28 * sizeof(float)>>>(
        x, w_off, b_off);
    dcn_main_kernel<<<dim3(2, H_, B_), 128, SM_TOTAL>>>(x, bias, out);
}

// round 7
// speedup vs baseline: 2.4351x; 1.3064x over previous
#include <cuda_runtime.h>
#include <math.h>
#include <stdint.h>

#define CHI 64
#define CHO 64
#define B_  4
#define H_  128
#define W_  256
#define HW  (H_*W_)

#define SAS 68          // smem row stride (floats)

// dcn_main smem: A 128x68, Bh 64x68, Bl 64x68
#define DM_A   0
#define DM_BH  8704
#define DM_BL  (8704 + 4352)
#define DM_TOTAL ((8704 + 4352 + 4352) * 4)     // 69632 B

// offset conv smem: A 128x68, Bh 32x68, Bl 32x68
#define OC_A   0
#define OC_BH  8704
#define OC_BL  (8704 + 2176)
#define OC_TOTAL ((8704 + 2176 + 2176) * 4)     // 52224 B

// scratch: offset/mask conv output [B, 27, H, W]
__device__ float g_om[(size_t)B_ * 27 * H_ * W_];
// main weight pre-split tf32: [tap][co][ci]
__device__ float g_wBh[9 * CHO * CHI];
__device__ float g_wBl[9 * CHO * CHI];
// offset weight pre-split tf32: [tap][32(oc pad)][ci]
__device__ float g_wOh[9 * 32 * CHI];
__device__ float g_wOl[9 * 32 * CHI];

// ---------------------------------------------------------------------------
__device__ __forceinline__ uint32_t f2tf32(float x) {
    uint32_t u; asm("cvt.rna.tf32.f32 %0, %1;" : "=r"(u) : "f"(x)); return u;
}
__device__ __forceinline__ void split_tf32(float v, uint32_t& hi, uint32_t& lo) {
    uint32_t h = f2tf32(v);
    float r = v - __uint_as_float(h);
    hi = h;
    lo = f2tf32(r);
}
__device__ __forceinline__ void mma8(float* d, const uint32_t* a,
                                     uint32_t b0, uint32_t b1) {
    asm volatile(
        "mma.sync.aligned.m16n8k8.row.col.f32.tf32.tf32.f32 "
        "{%0,%1,%2,%3}, {%4,%5,%6,%7}, {%8,%9}, {%0,%1,%2,%3};"
        : "+f"(d[0]), "+f"(d[1]), "+f"(d[2]), "+f"(d[3])
        : "r"(a[0]), "r"(a[1]), "r"(a[2]), "r"(a[3]), "r"(b0), "r"(b1));
}

// ---------------------------------------------------------------------------
// prep: split both weight tensors to tf32 hi/lo in GEMM-ready layouts
// ---------------------------------------------------------------------------
__global__ void prep_weights_kernel(const float* __restrict__ w,
                                    const float* __restrict__ w_off)
{
    int i = blockIdx.x * 256 + threadIdx.x;
    if (i < 9 * 64 * 64) {                        // main weight
        int tap = i / 4096;
        int rem = i - tap * 4096;
        int co  = rem >> 6;
        int ci  = rem & 63;
        float val = w[(co * 64 + ci) * 9 + tap];
        uint32_t hi, lo;
        split_tf32(val, hi, lo);
        g_wBh[tap * 4096 + co * 64 + ci] = __uint_as_float(hi);
        g_wBl[tap * 4096 + co * 64 + ci] = __uint_as_float(lo);
    } else if (i < 9 * 64 * 64 + 9 * 32 * 64) {   // offset weight (oc padded to 32)
        int j   = i - 9 * 64 * 64;
        int tap = j / 2048;
        int rem = j - tap * 2048;
        int oc  = rem >> 6;
        int ci  = rem & 63;
        float val = (oc < 27) ? w_off[(oc * 64 + ci) * 9 + tap] : 0.0f;
        uint32_t hi, lo;
        split_tf32(val, hi, lo);
        g_wOh[tap * 2048 + oc * 64 + ci] = __uint_as_float(hi);
        g_wOl[tap * 2048 + oc * 64 + ci] = __uint_as_float(lo);
    }
}

// ---------------------------------------------------------------------------
// Kernel 1: offset/mask conv as tf32 MMA implicit GEMM.
// Block = 128 threads = [128 pix (M)] x [32 oc (N), 27 used], K = 576.
// ---------------------------------------------------------------------------
__global__ __launch_bounds__(128, 4) void offset_conv_kernel(
    const float* __restrict__ x,
    const float* __restrict__ b_off)
{
    extern __shared__ float smf[];
    float* As  = smf + OC_A;
    float* Bhs = smf + OC_BH;
    float* Bls = smf + OC_BL;

    const int tid  = threadIdx.x;
    const int wid  = tid >> 5;
    const int lid  = tid & 31;
    const int g    = lid >> 2;
    const int t    = lid & 3;
    const int hblk = blockIdx.x;
    const int h    = blockIdx.y;
    const int b    = blockIdx.z;
    const int wo   = hblk * 128 + tid;

    const float* xb = x + (size_t)b * CHI * HW;

    float acc[2][4][4];
    #pragma unroll
    for (int m = 0; m < 2; m++)
        #pragma unroll
        for (int n = 0; n < 4; n++)
            #pragma unroll
            for (int e = 0; e < 4; e++) acc[m][n][e] = 0.0f;

    #pragma unroll 1
    for (int tap = 0; tap < 9; tap++) {
        if (tap) __syncthreads();

        // ---- copy pre-split B tiles [32oc][64ci] -> smem stride 68 ----
        {
            const float4* bh = (const float4*)(g_wOh + tap * 2048);
            const float4* bl = (const float4*)(g_wOl + tap * 2048);
            #pragma unroll
            for (int j = 0; j < 4; j++) {
                const int lin = tid + j * 128;      // 512 float4 total
                const int oc  = lin >> 4;
                const int c4  = lin & 15;
                *(float4*)(Bhs + oc * SAS + c4 * 4) = bh[lin];
                *(float4*)(Bls + oc * SAS + c4 * 4) = bl[lin];
            }
        }

        // ---- A tile: shifted input, zero-padded borders ----
        const int y  = h  - 1 + tap / 3;
        const int xv = wo - 1 + tap % 3;
        const bool valid = (y >= 0) && (y < H_) && (xv >= 0) && (xv < W_);
        const float* xp = xb + y * W_ + xv;
        #pragma unroll
        for (int j = 0; j < 16; j++) {
            float4 v4;
            #pragma unroll
            for (int e = 0; e < 4; e++)
                ((float*)&v4)[e] = valid ? __ldg(xp + (j * 4 + e) * HW) : 0.0f;
            *(float4*)(As + tid * SAS + j * 4) = v4;
        }

        __syncthreads();

        // ---- MMA: 8 k-steps x 4 n-frags x (2m x 3 terms) ----
        #pragma unroll 1
        for (int kk = 0; kk < 8; kk++) {
            const int col = kk * 8 + t;
            uint32_t ah[2][4], al[2][4];
            #pragma unroll
            for (int mi = 0; mi < 2; mi++) {
                const float* ab = As + (wid * 32 + mi * 16 + g) * SAS + col;
                split_tf32(ab[0],           ah[mi][0], al[mi][0]);
                split_tf32(ab[8 * SAS],     ah[mi][1], al[mi][1]);
                split_tf32(ab[4],           ah[mi][2], al[mi][2]);
                split_tf32(ab[8 * SAS + 4], ah[mi][3], al[mi][3]);
            }
            #pragma unroll
            for (int n = 0; n < 4; n++) {
                const float* bh = Bhs + (n * 8 + g) * SAS + col;
                const float* bl = Bls + (n * 8 + g) * SAS + col;
                const uint32_t bh0 = __float_as_uint(bh[0]);
                const uint32_t bh1 = __float_as_uint(bh[4]);
                const uint32_t bl0 = __float_as_uint(bl[0]);
                const uint32_t bl1 = __float_as_uint(bl[4]);
                mma8(acc[0][n], ah[0], bh0, bh1);
                mma8(acc[1][n], ah[1], bh0, bh1);
                mma8(acc[0][n], al[0], bh0, bh1);
                mma8(acc[1][n], al[1], bh0, bh1);
                mma8(acc[0][n], ah[0], bl0, bl1);
                mma8(acc[1][n], ah[1], bl0, bl1);
            }
        }
    }

    // ---- epilogue: stage through warp's own A region, write g_om ----
    float* ds = As + wid * 2176;      // [32 oc][34]
    #pragma unroll
    for (int mi = 0; mi < 2; mi++) {
        #pragma unroll
        for (int n = 0; n < 4; n++) {
            const int oc = n * 8 + 2 * t;
            const int p  = mi * 16 + g;
            ds[oc * 34 + p]           = acc[mi][n][0];
            ds[(oc + 1) * 34 + p]     = acc[mi][n][1];
            ds[oc * 34 + p + 8]       = acc[mi][n][2];
            ds[(oc + 1) * 34 + p + 8] = acc[mi][n][3];
        }
    }
    __syncwarp();

    const int pixbase = hblk * 128 + wid * 32;
    #pragma unroll
    for (int oc = 0; oc < 27; oc++) {
        g_om[((size_t)(b * 27 + oc) * H_ + h) * W_ + pixbase + lid] =
            ds[oc * 34 + lid] + __ldg(b_off + oc);
    }
}

// ---------------------------------------------------------------------------
// Kernel 2: deformable conv main GEMM on mma.sync tf32 (3-term split).
// B pre-split hi/lo in global; A split in-loop.
// ---------------------------------------------------------------------------
__global__ __launch_bounds__(128, 3) void dcn_main_kernel(
    const float* __restrict__ x,
    const float* __restrict__ bias,
    float* __restrict__ out)
{
    extern __shared__ float smf[];
    float* As  = smf + DM_A;
    float* Bhs = smf + DM_BH;
    float* Bls = smf + DM_BL;

    const int tid  = threadIdx.x;
    const int wid  = tid >> 5;
    const int lid  = tid & 31;
    const int g    = lid >> 2;
    const int t    = lid & 3;
    const int hblk = blockIdx.x;
    const int h    = blockIdx.y;
    const int b    = blockIdx.z;
    const int wo   = hblk * 128 + tid;

    const float* omp = g_om + ((size_t)b * 27 * H_ + h) * W_ + wo;
    const float* xb  = x + (size_t)b * CHI * HW;

    float acc[2][8][4];
    #pragma unroll
    for (int m = 0; m < 2; m++)
        #pragma unroll
        for (int n = 0; n < 8; n++)
            #pragma unroll
            for (int e = 0; e < 4; e++) acc[m][n][e] = 0.0f;

    #pragma unroll 1
    for (int tap = 0; tap < 9; tap++) {
        if (tap) __syncthreads();

        // ---- copy pre-split B tiles [64co][64ci] -> smem stride 68 ----
        {
            const float4* bh = (const float4*)(g_wBh + tap * 4096);
            const float4* bl = (const float4*)(g_wBl + tap * 4096);
            #pragma unroll
            for (int j = 0; j < 8; j++) {
                const int lin = tid + j * 128;      // 1024 float4 total
                const int co  = lin >> 4;
                const int c4  = lin & 15;
                *(float4*)(Bhs + co * SAS + c4 * 4) = bh[lin];
                *(float4*)(Bls + co * SAS + c4 * 4) = bl[lin];
            }
        }

        // ---- sampling params for this thread's pixel ----
        const float oy = omp[(size_t)(2 * tap)     * HW];
        const float ox = omp[(size_t)(2 * tap + 1) * HW];
        const float mz = omp[(size_t)(18 + tap)    * HW];
        const float m  = 1.0f / (1.0f + expf(-mz));

        const float sy = (float)(h  - 1 + tap / 3) + oy;
        const float sx = (float)(wo - 1 + tap % 3) + ox;

        const float y0f = floorf(sy);
        const float x0f = floorf(sx);
        const float dy  = sy - y0f;
        const float dx  = sx - x0f;
        const int y0 = (int)y0f, x0 = (int)x0f;
        const int y1 = y0 + 1,  x1 = x0 + 1;

        const bool vy0 = (y0 >= 0) && (y0 < H_);
        const bool vy1 = (y1 >= 0) && (y1 < H_);
        const bool vx0 = (x0 >= 0) && (x0 < W_);
        const bool vx1 = (x1 >= 0) && (x1 < W_);

        float w00 = (1.0f - dy) * (1.0f - dx) * m;
        float w01 = (1.0f - dy) * dx * m;
        float w10 = dy * (1.0f - dx) * m;
        float w11 = dy * dx * m;
        if (!(vy0 && vx0)) w00 = 0.0f;
        if (!(vy0 && vx1)) w01 = 0.0f;
        if (!(vy1 && vx0)) w10 = 0.0f;
        if (!(vy1 && vx1)) w11 = 0.0f;

        const int cy0 = min(max(y0, 0), H_ - 1);
        const int cy1 = min(max(y1, 0), H_ - 1);
        const int cx0 = min(max(x0, 0), W_ - 1);
        const int cx1 = min(max(x1, 0), W_ - 1);

        const float* p00 = xb + cy0 * W_ + cx0;
        const float* p01 = xb + cy0 * W_ + cx1;
        const float* p10 = xb + cy1 * W_ + cx0;
        const float* p11 = xb + cy1 * W_ + cx1;

        // ---- gather + bilinear: 64 ci for this pixel -> A[tid][ci] ----
        #pragma unroll
        for (int j = 0; j < 16; j++) {
            float4 v4;
            #pragma unroll
            for (int e = 0; e < 4; e++) {
                const int ci = j * 4 + e;
                ((float*)&v4)[e] = w00 * __ldg(p00 + ci * HW)
                                 + w01 * __ldg(p01 + ci * HW)
                                 + w10 * __ldg(p10 + ci * HW)
                                 + w11 * __ldg(p11 + ci * HW);
            }
            *(float4*)(As + tid * SAS + j * 4) = v4;
        }

        __syncthreads();

        // ---- MMA: 8 k-steps x 8 n-frags x (2m x 3 terms) ----
        #pragma unroll 1
        for (int kk = 0; kk < 8; kk++) {
            const int col = kk * 8 + t;
            uint32_t ah[2][4], al[2][4];
            #pragma unroll
            for (int mi = 0; mi < 2; mi++) {
                const float* ab = As + (wid * 32 + mi * 16 + g) * SAS + col;
                split_tf32(ab[0],           ah[mi][0], al[mi][0]);
                split_tf32(ab[8 * SAS],     ah[mi][1], al[mi][1]);
                split_tf32(ab[4],           ah[mi][2], al[mi][2]);
                split_tf32(ab[8 * SAS + 4], ah[mi][3], al[mi][3]);
            }
            #pragma unroll
            for (int n = 0; n < 8; n++) {
                const float* bh = Bhs + (n * 8 + g) * SAS + col;
                const float* bl = Bls + (n * 8 + g) * SAS + col;
                const uint32_t bh0 = __float_as_uint(bh[0]);
                const uint32_t bh1 = __float_as_uint(bh[4]);
                const uint32_t bl0 = __float_as_uint(bl[0]);
                const uint32_t bl1 = __float_as_uint(bl[4]);
                mma8(acc[0][n], ah[0], bh0, bh1);
                mma8(acc[1][n], ah[1], bh0, bh1);
                mma8(acc[0][n], al[0], bh0, bh1);
                mma8(acc[1][n], al[1], bh0, bh1);
                mma8(acc[0][n], ah[0], bl0, bl1);
                mma8(acc[1][n], ah[1], bl0, bl1);
            }
        }
    }

    // ---- epilogue: stage D through this warp's own A rows ----
    float* ds = As + wid * 2176;           // [64 co][34] per warp
    #pragma unroll
    for (int mi = 0; mi < 2; mi++) {
        #pragma unroll
        for (int n = 0; n < 8; n++) {
            const int co = n * 8 + 2 * t;
            const int p  = mi * 16 + g;
            ds[co * 34 + p]           = acc[mi][n][0];
            ds[(co + 1) * 34 + p]     = acc[mi][n][1];
            ds[co * 34 + p + 8]       = acc[mi][n][2];
            ds[(co + 1) * 34 + p + 8] = acc[mi][n][3];
        }
    }
    __syncwarp();

    const int pixbase = hblk * 128 + wid * 32;
    #pragma unroll 8
    for (int co = 0; co < 64; co++) {
        out[((size_t)(b * CHO + co) * H_ + h) * W_ + pixbase + lid] =
            ds[co * 34 + lid] + __ldg(bias + co);
    }
}

// ---------------------------------------------------------------------------
extern "C" void kernel_launch(void* const* d_in, const int* in_sizes, int n_in,
                              void* d_out, int out_size)
{
    const float* x      = (const float*)d_in[0];
    const float* w_off  = (const float*)d_in[1];
    const float* b_off  = (const float*)d_in[2];
    const float* weight = (const float*)d_in[3];
    const float* bias   = (const float*)d_in[4];
    float* out = (float*)d_out;

    cudaFuncSetAttribute(offset_conv_kernel,
                         cudaFuncAttributeMaxDynamicSharedMemorySize, OC_TOTAL);
    cudaFuncSetAttribute(dcn_main_kernel,
                         cudaFuncAttributeMaxDynamicSharedMemorySize, DM_TOTAL);

    const int prep_n = 9 * 64 * 64 + 9 * 32 * 64;
    prep_weights_kernel<<<(prep_n + 255) / 256, 256>>>(weight, w_off);
    offset_conv_kernel<<<dim3(2, H_, B_), 128, OC_TOTAL>>>(x, b_off);
    dcn_main_kernel<<<dim3(2, H_, B_), 128, DM_TOTAL>>>(x, bias, out);
}